// round 4
// baseline (speedup 1.0000x reference)
#include <cuda_runtime.h>
#include <math.h>

#define POOL    100
#define N_TASKS  10
#define P_LEN     8
#define EMB_D   768
#define BATCH   512
#define NBLK    197

#define D4      (EMB_D / 4)          // 192
#define N_XBLOCK ((long long)BATCH * NBLK * EMB_D)   // 77,414,400
#define N4      (N_XBLOCK / 4)       // 19,353,600 float4
#define V4_PER_THREAD 8
#define COPY_BLOCKS ((int)(N4 / (256 * V4_PER_THREAD)))  // 9,450 exact

// ---------------------------------------------------------------------------
// One fused kernel, register-capped so the copy path runs at full occupancy.
//   blocks [0, BATCH)                 : per-b sim + pmt (diag on the fly)
//   blocks [BATCH, BATCH+COPY_BLOCKS) : float4 x8 streaming copy of x_block
// ---------------------------------------------------------------------------
__global__ void __launch_bounds__(256, 8)
fused_kernel(const float* __restrict__ x_querry,
             const float4* __restrict__ x_block4,
             const float* __restrict__ e_a,
             const float* __restrict__ e_p,
             const int* __restrict__ task_id,
             float* __restrict__ out) {

    if (blockIdx.x >= BATCH) {
        // ------------------ streaming pass-through copy ------------------
        // 8 float4 per thread; all loads issued before stores (MLP=8)
        float4* dst = (float4*)(out + (size_t)2 * BATCH * (P_LEN / 2) * EMB_D);
        const long long base =
            (long long)(blockIdx.x - BATCH) * (256 * V4_PER_THREAD) + threadIdx.x;
        float4 v0 = __ldcs(&x_block4[base +    0]);
        float4 v1 = __ldcs(&x_block4[base +  256]);
        float4 v2 = __ldcs(&x_block4[base +  512]);
        float4 v3 = __ldcs(&x_block4[base +  768]);
        float4 v4 = __ldcs(&x_block4[base + 1024]);
        float4 v5 = __ldcs(&x_block4[base + 1280]);
        float4 v6 = __ldcs(&x_block4[base + 1536]);
        float4 v7 = __ldcs(&x_block4[base + 1792]);
        __stcs(&dst[base +    0], v0);
        __stcs(&dst[base +  256], v1);
        __stcs(&dst[base +  512], v2);
        __stcs(&dst[base +  768], v3);
        __stcs(&dst[base + 1024], v4);
        __stcs(&dst[base + 1280], v5);
        __stcs(&dst[base + 1536], v6);
        __stcs(&dst[base + 1792], v7);
        return;
    }

    // ------------------ per-b sim + pmt ------------------
    const int te = (task_id[0] + 1) * (POOL / N_TASKS);
    const int b = blockIdx.x;
    const int wid = threadIdx.x >> 5;
    const int lid = threadIdx.x & 31;

    __shared__ float sim_s[POOL];

    // one warp per k; warps stride over k
    for (int k = wid; k < te; k += 8) {
        const float4* __restrict__ x4 =
            (const float4*)(x_querry + ((size_t)b * POOL + (POOL - te + k)) * EMB_D);
        const float4* __restrict__ ea4 = (const float4*)(e_a + (size_t)k * EMB_D);
        const float4* __restrict__ ep4 = (const float4*)(e_p + (size_t)k * P_LEN * EMB_D);

        float sa = 0.f, sad = 0.f, sadd = 0.f;
        for (int d = lid; d < D4; d += 32) {
            float4 xv = x4[d];
            float4 ev = ea4[d];
            float ddx = 0.f, ddy = 0.f, ddz = 0.f, ddw = 0.f;
#pragma unroll
            for (int l = 0; l < P_LEN; ++l) {
                float4 p = ep4[l * D4 + d];
                ddx = fmaf(p.x, p.x, ddx);
                ddy = fmaf(p.y, p.y, ddy);
                ddz = fmaf(p.z, p.z, ddz);
                ddw = fmaf(p.w, p.w, ddw);
            }
            float a, a2;
            a = xv.x * ev.x; a2 = a * a; sa += a2; sad = fmaf(a2, ddx, sad); sadd = fmaf(a2 * ddx, ddx, sadd);
            a = xv.y * ev.y; a2 = a * a; sa += a2; sad = fmaf(a2, ddy, sad); sadd = fmaf(a2 * ddy, ddy, sadd);
            a = xv.z * ev.z; a2 = a * a; sa += a2; sad = fmaf(a2, ddz, sad); sadd = fmaf(a2 * ddz, ddz, sadd);
            a = xv.w * ev.w; a2 = a * a; sa += a2; sad = fmaf(a2, ddw, sad); sadd = fmaf(a2 * ddw, ddw, sadd);
        }
#pragma unroll
        for (int off = 16; off > 0; off >>= 1) {
            sa   += __shfl_down_sync(0xffffffffu, sa,   off);
            sad  += __shfl_down_sync(0xffffffffu, sad,  off);
            sadd += __shfl_down_sync(0xffffffffu, sadd, off);
        }
        if (lid == 0) {
            float na  = fmaxf(sqrtf(sa),   1e-12f);
            float nad = fmaxf(sqrtf(sadd), 1e-12f);
            sim_s[k] = sad / (na * nad);
        }
    }
    __syncthreads();

    // pmt: int_pmt[b,l,:] = sum_k sim_s[k] * e_p[k,l,:] ; split key/value
    const int NV = P_LEN * D4;           // 1536 float4
    const float4* __restrict__ ep4 = (const float4*)e_p;
    float4* __restrict__ out4 = (float4*)out;
    const size_t half4 = (size_t)BATCH * (P_LEN / 2) * D4;

    for (int v = threadIdx.x; v < NV; v += blockDim.x) {
        float4 acc = make_float4(0.f, 0.f, 0.f, 0.f);
        for (int k = 0; k < te; ++k) {
            const float s = sim_s[k];
            const float4 e = ep4[(size_t)k * NV + v];
            acc.x = fmaf(s, e.x, acc.x);
            acc.y = fmaf(s, e.y, acc.y);
            acc.z = fmaf(s, e.z, acc.z);
            acc.w = fmaf(s, e.w, acc.w);
        }
        const int l  = v / D4;
        const int d4 = v - l * D4;
        size_t off;
        if (l < P_LEN / 2) {
            off = ((size_t)b * (P_LEN / 2) + l) * D4 + d4;
        } else {
            off = half4 + ((size_t)b * (P_LEN / 2) + (l - P_LEN / 2)) * D4 + d4;
        }
        out4[off] = acc;
    }
}

extern "C" void kernel_launch(void* const* d_in, const int* in_sizes, int n_in,
                              void* d_out, int out_size) {
    const float* x_querry = (const float*)d_in[0];
    const float* x_block  = (const float*)d_in[1];
    const float* e_a      = (const float*)d_in[2];
    const float* e_p      = (const float*)d_in[3];
    const int*   task_id  = (const int*)d_in[5];

    float* out = (float*)d_out;

    fused_kernel<<<BATCH + COPY_BLOCKS, 256>>>(
        x_querry, (const float4*)x_block, e_a, e_p, task_id, out);
}